// round 15
// baseline (speedup 1.0000x reference)
#include <cuda_runtime.h>
#include <math.h>

#define NN 50000
#define EE 800000
#define DIN 128
#define HID 128
#define NHEADS 4
#define DHEAD 32
#define NEG_SLOPE 0.2f
#define LN_EPS 1e-5f
#define WPB 8   // warps (nodes) per block in node_kernel

// ---------------- scratch ----------------
__device__ float g_h[NN * HID];
__device__ float g_feat[NN * HID];
__device__ float g_el[NN * NHEADS];
__device__ float g_er[NN * NHEADS];
__device__ int   g_count[NN];
__device__ int   g_cursor[NN];
__device__ int   g_rowstart[NN + 1];
__device__ int   g_csrc[EE];

__device__ __forceinline__ float leaky(float v) {
    return v >= 0.f ? v : NEG_SLOPE * v;
}

// ---------------- CSR build ----------------
__global__ void zero_counts() {
    int i = blockIdx.x * blockDim.x + threadIdx.x;
    if (i < NN) g_count[i] = 0;
}

__global__ void hist_kernel(const int* __restrict__ dst) {
    int e = blockIdx.x * blockDim.x + threadIdx.x;
    if (e < EE) atomicAdd(&g_count[dst[e]], 1);
}

// single block, 1024 threads: exclusive scan over g_count -> g_rowstart, g_cursor
__global__ void scan_kernel() {
    const int T = 1024;
    const int CH = (NN + T - 1) / T;  // 49
    int t = threadIdx.x;
    int base = t * CH;
    int sum = 0;
    for (int i = 0; i < CH; i++) {
        int idx = base + i;
        if (idx < NN) sum += g_count[idx];
    }
    __shared__ int sm[T];
    sm[t] = sum;
    __syncthreads();
    for (int off = 1; off < T; off <<= 1) {
        int v = (t >= off) ? sm[t - off] : 0;
        __syncthreads();
        sm[t] += v;
        __syncthreads();
    }
    int run = sm[t] - sum;
    for (int i = 0; i < CH; i++) {
        int idx = base + i;
        if (idx < NN) {
            g_rowstart[idx] = run;
            g_cursor[idx] = run;
            run += g_count[idx];
        }
    }
    if (t == T - 1) g_rowstart[NN] = sm[T - 1];
}

__global__ void scatter_kernel(const int* __restrict__ src,
                               const int* __restrict__ dst) {
    int e = blockIdx.x * blockDim.x + threadIdx.x;
    if (e < EE) {
        int pos = atomicAdd(&g_cursor[dst[e]], 1);
        g_csrc[pos] = src[e];
    }
}

// ---------------- GEMM (128x128 tile, 8x8 per thread) + fused el/er ----------
#define TM 128
#define TK 16

__global__ void __launch_bounds__(256) gemm_elr_kernel(
        const float* __restrict__ X,
        const float* __restrict__ W,
        const float* __restrict__ al,
        const float* __restrict__ ar) {
    __shared__ float xs[TK][TM + 4];  // transposed: xs[k][row]
    __shared__ float ws[TK][HID];     // ws[k][col]
    int t = threadIdx.x;              // 256
    int tx = t & 15;                  // col group (cols tx*8 .. +8)
    int ty = t >> 4;                  // row group (rows ty*8 .. +8)
    int row0 = blockIdx.x * TM;

    int head = tx >> 2;               // cols tx*8..tx*8+7 all in head tx>>2
    int sub = (tx & 3) * 8;           // offset within head's 32 cols

    float al8[8], ar8[8];
#pragma unroll
    for (int j = 0; j < 8; j++) {
        al8[j] = al[head * DHEAD + sub + j];
        ar8[j] = ar[head * DHEAD + sub + j];
    }

    float acc[8][8];
#pragma unroll
    for (int i = 0; i < 8; i++)
#pragma unroll
        for (int j = 0; j < 8; j++) acc[i][j] = 0.f;

    for (int k0 = 0; k0 < DIN; k0 += TK) {
        // stage X tile (128 rows x 16 cols) transposed into xs
#pragma unroll
        for (int i = 0; i < 2; i++) {
            int idx = t * 2 + i;       // 0..511
            int r = idx >> 2;          // row 0..127
            int q = idx & 3;           // float4 within the 16-col slab
            int gr = row0 + r;
            float4 v = make_float4(0.f, 0.f, 0.f, 0.f);
            if (gr < NN) v = ((const float4*)X)[gr * (DIN / 4) + (k0 / 4) + q];
            xs[q * 4 + 0][r] = v.x;
            xs[q * 4 + 1][r] = v.y;
            xs[q * 4 + 2][r] = v.z;
            xs[q * 4 + 3][r] = v.w;
        }
        // stage W tile (16 rows x 128 cols)
#pragma unroll
        for (int i = 0; i < 2; i++) {
            int idx = t * 2 + i;       // 0..511
            int k = idx >> 5;          // 0..15
            int q = idx & 31;          // float4 col
            float4 v = ((const float4*)W)[(k0 + k) * (HID / 4) + q];
            ((float4*)ws[k])[q] = v;
        }
        __syncthreads();
#pragma unroll
        for (int k = 0; k < TK; k++) {
            float a[8], bb[8];
            *(float4*)&a[0] = *(const float4*)&xs[k][ty * 8];
            *(float4*)&a[4] = *(const float4*)&xs[k][ty * 8 + 4];
            *(float4*)&bb[0] = *(const float4*)&ws[k][tx * 8];
            *(float4*)&bb[4] = *(const float4*)&ws[k][tx * 8 + 4];
#pragma unroll
            for (int i = 0; i < 8; i++)
#pragma unroll
                for (int j = 0; j < 8; j++) acc[i][j] += a[i] * bb[j];
        }
        __syncthreads();
    }

    // epilogue: store h, compute el/er
#pragma unroll
    for (int i = 0; i < 8; i++) {
        int gr = row0 + ty * 8 + i;
        if (gr < NN) {
            float4 h0 = make_float4(acc[i][0], acc[i][1], acc[i][2], acc[i][3]);
            float4 h1 = make_float4(acc[i][4], acc[i][5], acc[i][6], acc[i][7]);
            ((float4*)g_h)[gr * 32 + tx * 2] = h0;
            ((float4*)g_h)[gr * 32 + tx * 2 + 1] = h1;

            float vl = 0.f, vr = 0.f;
#pragma unroll
            for (int j = 0; j < 8; j++) {
                vl += acc[i][j] * al8[j];
                vr += acc[i][j] * ar8[j];
            }
            vl += __shfl_xor_sync(0xffffffffu, vl, 1);
            vr += __shfl_xor_sync(0xffffffffu, vr, 1);
            vl += __shfl_xor_sync(0xffffffffu, vl, 2);
            vr += __shfl_xor_sync(0xffffffffu, vr, 2);
            if ((tx & 3) == 0) {
                g_el[gr * NHEADS + head] = vl;
                g_er[gr * NHEADS + head] = vr;
            }
        }
    }
}

// ---------------- warp-per-node gather + softmax + aggregate + LN + ELU --------
// One warp per dst node; lane owns feature cols [4*lane, 4*lane+4), head = lane>>3.
// Edge loop unrolled x8 to raise per-warp MLP (~24 outstanding L2 loads).
__global__ void __launch_bounds__(WPB * 32) node_kernel(
        const float* __restrict__ b,
        const float* __restrict__ g,
        const float* __restrict__ be,
        float* __restrict__ out) {
    int warp = threadIdx.x >> 5;
    int n = blockIdx.x * WPB + warp;
    if (n >= NN) return;
    int lane = threadIdx.x & 31;
    int head = lane >> 3;

    int beg = g_rowstart[n];
    int end = g_rowstart[n + 1];

    float er_h = g_er[n * NHEADS + head];

    float4 acc = make_float4(0.f, 0.f, 0.f, 0.f);
    float denom = 0.f;

    const float4* __restrict__ h4 = (const float4*)g_h;
    int col4 = lane;

    int k = beg;
    for (; k + 8 <= end; k += 8) {
        int s0 = g_csrc[k];
        int s1 = g_csrc[k + 1];
        int s2 = g_csrc[k + 2];
        int s3 = g_csrc[k + 3];
        int s4 = g_csrc[k + 4];
        int s5 = g_csrc[k + 5];
        int s6 = g_csrc[k + 6];
        int s7 = g_csrc[k + 7];
        float e0 = g_el[s0 * NHEADS + head];
        float e1 = g_el[s1 * NHEADS + head];
        float e2 = g_el[s2 * NHEADS + head];
        float e3 = g_el[s3 * NHEADS + head];
        float e4 = g_el[s4 * NHEADS + head];
        float e5 = g_el[s5 * NHEADS + head];
        float e6 = g_el[s6 * NHEADS + head];
        float e7 = g_el[s7 * NHEADS + head];
        float4 h0 = h4[s0 * 32 + col4];
        float4 h1 = h4[s1 * 32 + col4];
        float4 h2 = h4[s2 * 32 + col4];
        float4 h3 = h4[s3 * 32 + col4];
        float4 h4v = h4[s4 * 32 + col4];
        float4 h5 = h4[s5 * 32 + col4];
        float4 h6 = h4[s6 * 32 + col4];
        float4 h7 = h4[s7 * 32 + col4];
        float w0 = __expf(leaky(e0 + er_h));
        float w1 = __expf(leaky(e1 + er_h));
        float w2 = __expf(leaky(e2 + er_h));
        float w3 = __expf(leaky(e3 + er_h));
        float w4 = __expf(leaky(e4 + er_h));
        float w5 = __expf(leaky(e5 + er_h));
        float w6 = __expf(leaky(e6 + er_h));
        float w7 = __expf(leaky(e7 + er_h));
        denom += w0 + w1 + w2 + w3 + w4 + w5 + w6 + w7;
        acc.x += h0.x * w0; acc.y += h0.y * w0; acc.z += h0.z * w0; acc.w += h0.w * w0;
        acc.x += h1.x * w1; acc.y += h1.y * w1; acc.z += h1.z * w1; acc.w += h1.w * w1;
        acc.x += h2.x * w2; acc.y += h2.y * w2; acc.z += h2.z * w2; acc.w += h2.w * w2;
        acc.x += h3.x * w3; acc.y += h3.y * w3; acc.z += h3.z * w3; acc.w += h3.w * w3;
        acc.x += h4v.x * w4; acc.y += h4v.y * w4; acc.z += h4v.z * w4; acc.w += h4v.w * w4;
        acc.x += h5.x * w5; acc.y += h5.y * w5; acc.z += h5.z * w5; acc.w += h5.w * w5;
        acc.x += h6.x * w6; acc.y += h6.y * w6; acc.z += h6.z * w6; acc.w += h6.w * w6;
        acc.x += h7.x * w7; acc.y += h7.y * w7; acc.z += h7.z * w7; acc.w += h7.w * w7;
    }
    for (; k + 4 <= end; k += 4) {
        int s0 = g_csrc[k];
        int s1 = g_csrc[k + 1];
        int s2 = g_csrc[k + 2];
        int s3 = g_csrc[k + 3];
        float e0 = g_el[s0 * NHEADS + head];
        float e1 = g_el[s1 * NHEADS + head];
        float e2 = g_el[s2 * NHEADS + head];
        float e3 = g_el[s3 * NHEADS + head];
        float4 h0 = h4[s0 * 32 + col4];
        float4 h1 = h4[s1 * 32 + col4];
        float4 h2 = h4[s2 * 32 + col4];
        float4 h3 = h4[s3 * 32 + col4];
        float w0 = __expf(leaky(e0 + er_h));
        float w1 = __expf(leaky(e1 + er_h));
        float w2 = __expf(leaky(e2 + er_h));
        float w3 = __expf(leaky(e3 + er_h));
        denom += w0 + w1 + w2 + w3;
        acc.x += h0.x * w0; acc.y += h0.y * w0; acc.z += h0.z * w0; acc.w += h0.w * w0;
        acc.x += h1.x * w1; acc.y += h1.y * w1; acc.z += h1.z * w1; acc.w += h1.w * w1;
        acc.x += h2.x * w2; acc.y += h2.y * w2; acc.z += h2.z * w2; acc.w += h2.w * w2;
        acc.x += h3.x * w3; acc.y += h3.y * w3; acc.z += h3.z * w3; acc.w += h3.w * w3;
    }
    for (; k < end; k++) {
        int s = g_csrc[k];
        float w = __expf(leaky(g_el[s * NHEADS + head] + er_h));
        float4 h = h4[s * 32 + col4];
        denom += w;
        acc.x += h.x * w; acc.y += h.y * w; acc.z += h.z * w; acc.w += h.w * w;
    }

    float invd = 1.f / fmaxf(denom, 1e-9f);

    float4 b4 = ((const float4*)b)[lane];
    float4 v;
    v.x = acc.x * invd + b4.x;
    v.y = acc.y * invd + b4.y;
    v.z = acc.z * invd + b4.z;
    v.w = acc.w * invd + b4.w;

    float s1 = v.x + v.y + v.z + v.w;
#pragma unroll
    for (int o = 16; o > 0; o >>= 1) s1 += __shfl_xor_sync(0xffffffffu, s1, o);
    float mu = s1 * (1.f / HID);

    float cx = v.x - mu, cy = v.y - mu, cz = v.z - mu, cw = v.w - mu;
    float s2 = cx * cx + cy * cy + cz * cz + cw * cw;
#pragma unroll
    for (int o = 16; o > 0; o >>= 1) s2 += __shfl_xor_sync(0xffffffffu, s2, o);
    float rstd = rsqrtf(s2 * (1.f / HID) + LN_EPS);

    float4 g4 = ((const float4*)g)[lane];
    float4 be4 = ((const float4*)be)[lane];
    float4 y;
    y.x = cx * rstd * g4.x + be4.x;
    y.y = cy * rstd * g4.y + be4.y;
    y.z = cz * rstd * g4.z + be4.z;
    y.w = cw * rstd * g4.w + be4.w;
    y.x = y.x > 0.f ? y.x : expm1f(y.x);
    y.y = y.y > 0.f ? y.y : expm1f(y.y);
    y.z = y.z > 0.f ? y.z : expm1f(y.z);
    y.w = y.w > 0.f ? y.w : expm1f(y.w);

    ((float4*)out)[n * 32 + lane] = y;
}

// ---------------- launch ----------------
extern "C" void kernel_launch(void* const* d_in, const int* in_sizes, int n_in,
                              void* d_out, int out_size) {
    const float* features = (const float*)d_in[0];
    const int* src = (const int*)d_in[1];
    const int* dst = (const int*)d_in[2];
    const float* W0 = (const float*)d_in[3];
    const float* al0 = (const float*)d_in[4];
    const float* ar0 = (const float*)d_in[5];
    const float* b0 = (const float*)d_in[6];
    const float* g0 = (const float*)d_in[7];
    const float* be0 = (const float*)d_in[8];
    const float* W1 = (const float*)d_in[9];
    const float* al1 = (const float*)d_in[10];
    const float* ar1 = (const float*)d_in[11];
    const float* b1 = (const float*)d_in[12];
    const float* g1 = (const float*)d_in[13];
    const float* be1 = (const float*)d_in[14];
    float* out = (float*)d_out;

    static cudaStream_t s2 = nullptr;
    static cudaEvent_t evFork = nullptr, evJoin = nullptr;
    if (!s2) {
        cudaStreamCreateWithFlags(&s2, cudaStreamNonBlocking);
        cudaEventCreateWithFlags(&evFork, cudaEventDisableTiming);
        cudaEventCreateWithFlags(&evJoin, cudaEventDisableTiming);
    }

    float* feat_ptr = nullptr;
    cudaGetSymbolAddress((void**)&feat_ptr, g_feat);

    const int gemm_grid = (NN + TM - 1) / TM;

    // fork: CSR build on s2, concurrent with layer-0 GEMM on the main stream
    cudaEventRecord(evFork, 0);
    cudaStreamWaitEvent(s2, evFork, 0);
    zero_counts<<<(NN + 255) / 256, 256, 0, s2>>>();
    hist_kernel<<<(EE + 255) / 256, 256, 0, s2>>>(dst);
    scan_kernel<<<1, 1024, 0, s2>>>();
    scatter_kernel<<<(EE + 255) / 256, 256, 0, s2>>>(src, dst);
    cudaEventRecord(evJoin, s2);

    gemm_elr_kernel<<<gemm_grid, 256>>>(features, W0, al0, ar0);
    cudaStreamWaitEvent(0, evJoin, 0);  // join before aggregation needs CSR

    node_kernel<<<(NN + WPB - 1) / WPB, WPB * 32>>>(b0, g0, be0, feat_ptr);

    gemm_elr_kernel<<<gemm_grid, 256>>>(feat_ptr, W1, al1, ar1);
    node_kernel<<<(NN + WPB - 1) / WPB, WPB * 32>>>(b1, g1, be1, out);
}

// round 16
// speedup vs baseline: 1.5741x; 1.5741x over previous
#include <cuda_runtime.h>
#include <cuda_fp16.h>
#include <math.h>

#define NN 50000
#define EE 800000
#define DIN 128
#define HID 128
#define NHEADS 4
#define DHEAD 32
#define NEG_SLOPE 0.2f
#define LN_EPS 1e-5f
#define WPB 8   // warps (nodes) per block in node_kernel

// ---------------- scratch ----------------
__device__ __half g_hh[NN * HID];     // fp16 projections (gather payload)
__device__ float g_feat[NN * HID];
__device__ float g_el[NN * NHEADS];
__device__ float g_er[NN * NHEADS];
__device__ int   g_count[NN];
__device__ int   g_cursor[NN];
__device__ int   g_rowstart[NN + 1];
__device__ int   g_csrc[EE];

__device__ __forceinline__ float leaky(float v) {
    return v >= 0.f ? v : NEG_SLOPE * v;
}

// ---------------- CSR build ----------------
__global__ void zero_counts() {
    int i = blockIdx.x * blockDim.x + threadIdx.x;
    if (i < NN) g_count[i] = 0;
}

__global__ void hist_kernel(const int* __restrict__ dst) {
    int e = blockIdx.x * blockDim.x + threadIdx.x;
    if (e < EE) atomicAdd(&g_count[dst[e]], 1);
}

// single block, 1024 threads: exclusive scan over g_count -> g_rowstart, g_cursor
__global__ void scan_kernel() {
    const int T = 1024;
    const int CH = (NN + T - 1) / T;  // 49
    int t = threadIdx.x;
    int base = t * CH;
    int sum = 0;
    for (int i = 0; i < CH; i++) {
        int idx = base + i;
        if (idx < NN) sum += g_count[idx];
    }
    __shared__ int sm[T];
    sm[t] = sum;
    __syncthreads();
    for (int off = 1; off < T; off <<= 1) {
        int v = (t >= off) ? sm[t - off] : 0;
        __syncthreads();
        sm[t] += v;
        __syncthreads();
    }
    int run = sm[t] - sum;
    for (int i = 0; i < CH; i++) {
        int idx = base + i;
        if (idx < NN) {
            g_rowstart[idx] = run;
            g_cursor[idx] = run;
            run += g_count[idx];
        }
    }
    if (t == T - 1) g_rowstart[NN] = sm[T - 1];
}

__global__ void scatter_kernel(const int* __restrict__ src,
                               const int* __restrict__ dst) {
    int e = blockIdx.x * blockDim.x + threadIdx.x;
    if (e < EE) {
        int pos = atomicAdd(&g_cursor[dst[e]], 1);
        g_csrc[pos] = src[e];
    }
}

// ---------------- GEMM (128x128 tile, 8x8 per thread) + fused el/er ----------
#define TM 128
#define TK 16

__global__ void __launch_bounds__(256) gemm_elr_kernel(
        const float* __restrict__ X,
        const float* __restrict__ W,
        const float* __restrict__ al,
        const float* __restrict__ ar) {
    __shared__ float xs[TK][TM + 4];  // transposed: xs[k][row]
    __shared__ float ws[TK][HID];     // ws[k][col]
    int t = threadIdx.x;              // 256
    int tx = t & 15;                  // col group (cols tx*8 .. +8)
    int ty = t >> 4;                  // row group (rows ty*8 .. +8)
    int row0 = blockIdx.x * TM;

    int head = tx >> 2;               // cols tx*8..tx*8+7 all in head tx>>2
    int sub = (tx & 3) * 8;           // offset within head's 32 cols

    float al8[8], ar8[8];
#pragma unroll
    for (int j = 0; j < 8; j++) {
        al8[j] = al[head * DHEAD + sub + j];
        ar8[j] = ar[head * DHEAD + sub + j];
    }

    float acc[8][8];
#pragma unroll
    for (int i = 0; i < 8; i++)
#pragma unroll
        for (int j = 0; j < 8; j++) acc[i][j] = 0.f;

    for (int k0 = 0; k0 < DIN; k0 += TK) {
        // stage X tile (128 rows x 16 cols) transposed into xs
#pragma unroll
        for (int i = 0; i < 2; i++) {
            int idx = t * 2 + i;       // 0..511
            int r = idx >> 2;          // row 0..127
            int q = idx & 3;           // float4 within the 16-col slab
            int gr = row0 + r;
            float4 v = make_float4(0.f, 0.f, 0.f, 0.f);
            if (gr < NN) v = ((const float4*)X)[gr * (DIN / 4) + (k0 / 4) + q];
            xs[q * 4 + 0][r] = v.x;
            xs[q * 4 + 1][r] = v.y;
            xs[q * 4 + 2][r] = v.z;
            xs[q * 4 + 3][r] = v.w;
        }
        // stage W tile (16 rows x 128 cols)
#pragma unroll
        for (int i = 0; i < 2; i++) {
            int idx = t * 2 + i;       // 0..511
            int k = idx >> 5;          // 0..15
            int q = idx & 31;          // float4 col
            float4 v = ((const float4*)W)[(k0 + k) * (HID / 4) + q];
            ((float4*)ws[k])[q] = v;
        }
        __syncthreads();
#pragma unroll
        for (int k = 0; k < TK; k++) {
            float a[8], bb[8];
            *(float4*)&a[0] = *(const float4*)&xs[k][ty * 8];
            *(float4*)&a[4] = *(const float4*)&xs[k][ty * 8 + 4];
            *(float4*)&bb[0] = *(const float4*)&ws[k][tx * 8];
            *(float4*)&bb[4] = *(const float4*)&ws[k][tx * 8 + 4];
#pragma unroll
            for (int i = 0; i < 8; i++)
#pragma unroll
                for (int j = 0; j < 8; j++) acc[i][j] += a[i] * bb[j];
        }
        __syncthreads();
    }

    // epilogue: store h (fp16), compute el/er (fp32)
#pragma unroll
    for (int i = 0; i < 8; i++) {
        int gr = row0 + ty * 8 + i;
        if (gr < NN) {
            union { __half2 h2[4]; uint4 u; } cv;
            cv.h2[0] = __float22half2_rn(make_float2(acc[i][0], acc[i][1]));
            cv.h2[1] = __float22half2_rn(make_float2(acc[i][2], acc[i][3]));
            cv.h2[2] = __float22half2_rn(make_float2(acc[i][4], acc[i][5]));
            cv.h2[3] = __float22half2_rn(make_float2(acc[i][6], acc[i][7]));
            // row = 128 half = 256 B = 16 uint4; this thread owns uint4 #tx
            ((uint4*)g_hh)[gr * 16 + tx] = cv.u;

            float vl = 0.f, vr = 0.f;
#pragma unroll
            for (int j = 0; j < 8; j++) {
                vl += acc[i][j] * al8[j];
                vr += acc[i][j] * ar8[j];
            }
            vl += __shfl_xor_sync(0xffffffffu, vl, 1);
            vr += __shfl_xor_sync(0xffffffffu, vr, 1);
            vl += __shfl_xor_sync(0xffffffffu, vl, 2);
            vr += __shfl_xor_sync(0xffffffffu, vr, 2);
            if ((tx & 3) == 0) {
                g_el[gr * NHEADS + head] = vl;
                g_er[gr * NHEADS + head] = vr;
            }
        }
    }
}

// ---------------- warp-per-node gather + softmax + aggregate + LN + ELU --------
// One warp per dst node; lane owns feature cols [4*lane, 4*lane+4), head = lane>>3.
// h gathered as fp16 (8 B/lane/edge), accumulated in fp32.
__global__ void __launch_bounds__(WPB * 32) node_kernel(
        const float* __restrict__ b,
        const float* __restrict__ g,
        const float* __restrict__ be,
        float* __restrict__ out) {
    int warp = threadIdx.x >> 5;
    int n = blockIdx.x * WPB + warp;
    if (n >= NN) return;
    int lane = threadIdx.x & 31;
    int head = lane >> 3;

    int beg = g_rowstart[n];
    int end = g_rowstart[n + 1];

    float er_h = g_er[n * NHEADS + head];

    float4 acc = make_float4(0.f, 0.f, 0.f, 0.f);
    float denom = 0.f;

    const uint2* __restrict__ h2p = (const uint2*)g_hh;  // row = 32 uint2

    int k = beg;
    for (; k + 4 <= end; k += 4) {
        int s0 = g_csrc[k];
        int s1 = g_csrc[k + 1];
        int s2 = g_csrc[k + 2];
        int s3 = g_csrc[k + 3];
        float e0 = g_el[s0 * NHEADS + head];
        float e1 = g_el[s1 * NHEADS + head];
        float e2 = g_el[s2 * NHEADS + head];
        float e3 = g_el[s3 * NHEADS + head];
        uint2 r0 = h2p[s0 * 32 + lane];
        uint2 r1 = h2p[s1 * 32 + lane];
        uint2 r2 = h2p[s2 * 32 + lane];
        uint2 r3 = h2p[s3 * 32 + lane];
        float w0 = __expf(leaky(e0 + er_h));
        float w1 = __expf(leaky(e1 + er_h));
        float w2 = __expf(leaky(e2 + er_h));
        float w3 = __expf(leaky(e3 + er_h));
        denom += w0 + w1 + w2 + w3;
        float2 a0 = __half22float2(*(__half2*)&r0.x);
        float2 b0v = __half22float2(*(__half2*)&r0.y);
        float2 a1 = __half22float2(*(__half2*)&r1.x);
        float2 b1v = __half22float2(*(__half2*)&r1.y);
        float2 a2 = __half22float2(*(__half2*)&r2.x);
        float2 b2v = __half22float2(*(__half2*)&r2.y);
        float2 a3 = __half22float2(*(__half2*)&r3.x);
        float2 b3v = __half22float2(*(__half2*)&r3.y);
        acc.x += a0.x * w0; acc.y += a0.y * w0; acc.z += b0v.x * w0; acc.w += b0v.y * w0;
        acc.x += a1.x * w1; acc.y += a1.y * w1; acc.z += b1v.x * w1; acc.w += b1v.y * w1;
        acc.x += a2.x * w2; acc.y += a2.y * w2; acc.z += b2v.x * w2; acc.w += b2v.y * w2;
        acc.x += a3.x * w3; acc.y += a3.y * w3; acc.z += b3v.x * w3; acc.w += b3v.y * w3;
    }
    for (; k < end; k++) {
        int s = g_csrc[k];
        float w = __expf(leaky(g_el[s * NHEADS + head] + er_h));
        uint2 r = h2p[s * 32 + lane];
        float2 a = __half22float2(*(__half2*)&r.x);
        float2 bv = __half22float2(*(__half2*)&r.y);
        denom += w;
        acc.x += a.x * w; acc.y += a.y * w; acc.z += bv.x * w; acc.w += bv.y * w;
    }

    float invd = 1.f / fmaxf(denom, 1e-9f);

    float4 b4 = ((const float4*)b)[lane];
    float4 v;
    v.x = acc.x * invd + b4.x;
    v.y = acc.y * invd + b4.y;
    v.z = acc.z * invd + b4.z;
    v.w = acc.w * invd + b4.w;

    float s1 = v.x + v.y + v.z + v.w;
#pragma unroll
    for (int o = 16; o > 0; o >>= 1) s1 += __shfl_xor_sync(0xffffffffu, s1, o);
    float mu = s1 * (1.f / HID);

    float cx = v.x - mu, cy = v.y - mu, cz = v.z - mu, cw = v.w - mu;
    float s2 = cx * cx + cy * cy + cz * cz + cw * cw;
#pragma unroll
    for (int o = 16; o > 0; o >>= 1) s2 += __shfl_xor_sync(0xffffffffu, s2, o);
    float rstd = rsqrtf(s2 * (1.f / HID) + LN_EPS);

    float4 g4 = ((const float4*)g)[lane];
    float4 be4 = ((const float4*)be)[lane];
    float4 y;
    y.x = cx * rstd * g4.x + be4.x;
    y.y = cy * rstd * g4.y + be4.y;
    y.z = cz * rstd * g4.z + be4.z;
    y.w = cw * rstd * g4.w + be4.w;
    y.x = y.x > 0.f ? y.x : expm1f(y.x);
    y.y = y.y > 0.f ? y.y : expm1f(y.y);
    y.z = y.z > 0.f ? y.z : expm1f(y.z);
    y.w = y.w > 0.f ? y.w : expm1f(y.w);

    ((float4*)out)[n * 32 + lane] = y;
}

// ---------------- launch ----------------
extern "C" void kernel_launch(void* const* d_in, const int* in_sizes, int n_in,
                              void* d_out, int out_size) {
    const float* features = (const float*)d_in[0];
    const int* src = (const int*)d_in[1];
    const int* dst = (const int*)d_in[2];
    const float* W0 = (const float*)d_in[3];
    const float* al0 = (const float*)d_in[4];
    const float* ar0 = (const float*)d_in[5];
    const float* b0 = (const float*)d_in[6];
    const float* g0 = (const float*)d_in[7];
    const float* be0 = (const float*)d_in[8];
    const float* W1 = (const float*)d_in[9];
    const float* al1 = (const float*)d_in[10];
    const float* ar1 = (const float*)d_in[11];
    const float* b1 = (const float*)d_in[12];
    const float* g1 = (const float*)d_in[13];
    const float* be1 = (const float*)d_in[14];
    float* out = (float*)d_out;

    static cudaStream_t s2 = nullptr;
    static cudaEvent_t evFork = nullptr, evJoin = nullptr;
    if (!s2) {
        cudaStreamCreateWithFlags(&s2, cudaStreamNonBlocking);
        cudaEventCreateWithFlags(&evFork, cudaEventDisableTiming);
        cudaEventCreateWithFlags(&evJoin, cudaEventDisableTiming);
    }

    float* feat_ptr = nullptr;
    cudaGetSymbolAddress((void**)&feat_ptr, g_feat);

    const int gemm_grid = (NN + TM - 1) / TM;

    // fork: CSR build on s2, concurrent with layer-0 GEMM on the main stream
    cudaEventRecord(evFork, 0);
    cudaStreamWaitEvent(s2, evFork, 0);
    zero_counts<<<(NN + 255) / 256, 256, 0, s2>>>();
    hist_kernel<<<(EE + 255) / 256, 256, 0, s2>>>(dst);
    scan_kernel<<<1, 1024, 0, s2>>>();
    scatter_kernel<<<(EE + 255) / 256, 256, 0, s2>>>(src, dst);
    cudaEventRecord(evJoin, s2);

    gemm_elr_kernel<<<gemm_grid, 256>>>(features, W0, al0, ar0);
    cudaStreamWaitEvent(0, evJoin, 0);  // join before aggregation needs CSR

    node_kernel<<<(NN + WPB - 1) / WPB, WPB * 32>>>(b0, g0, be0, feat_ptr);

    gemm_elr_kernel<<<gemm_grid, 256>>>(feat_ptr, W1, al1, ar1);
    node_kernel<<<(NN + WPB - 1) / WPB, WPB * 32>>>(b1, g1, be1, out);
}